// round 10
// baseline (speedup 1.0000x reference)
#include <cuda_runtime.h>
#include <cstdint>

#define NN 4096
#define FF 128
#define HH 8
#define DD 8
#define HD 64
#define ECAP 72     // fast-path edge cap (mean E~41, sigma~6.4; slow fallback keeps correctness for outliers)
#define FPAD 72     // s_feats row stride: 72 mod 32 == 8 -> stripes/dims hit 32 distinct banks (conflict-free)

__device__ float g_feats[NN * HD];
__device__ float g_as[NN * HH];
__device__ float g_an[NN * HH];

__device__ __forceinline__ void cp_async4(uint32_t dst, const void* src) {
    asm volatile("cp.async.ca.shared.global [%0], [%1], 4;" :: "r"(dst), "l"(src));
}
__device__ __forceinline__ void cp_async16(uint32_t dst, const void* src) {
    asm volatile("cp.async.ca.shared.global [%0], [%1], 16;" :: "r"(dst), "l"(src));
}
__device__ __forceinline__ void cp_async_commit() {
    asm volatile("cp.async.commit_group;");
}
__device__ __forceinline__ void cp_async_wait0() {
    asm volatile("cp.async.wait_group 0;");
}

// ---------------- Kernel 1: feats = X @ W  fused with a_s / a_n epilogue ----------------
__global__ __launch_bounds__(256) void feats_att_kernel(const float* __restrict__ X,
                                                        const float* __restrict__ W,
                                                        const float* __restrict__ att_self,
                                                        const float* __restrict__ att_neigh) {
    __shared__ float Ws[FF][HD];      // 32 KB
    __shared__ float Xs[16][133];     // stride 133; reused as Fs[16][68] in epilogue
    const int tid = threadIdx.x;
    const int rbase = blockIdx.x * 16;

    {
        const float4* Wv = (const float4*)W;
        float4* Wsv = (float4*)&Ws[0][0];
        #pragma unroll
        for (int k = 0; k < 8; ++k) Wsv[tid + k * 256] = Wv[tid + k * 256];
    }
    {
        #pragma unroll
        for (int k = 0; k < 2; ++k) {
            const int li = tid + k * 256;
            const int r = li >> 5;
            const int c4 = (li & 31) << 2;
            float4 v = *(const float4*)&X[(rbase + r) * FF + c4];
            Xs[r][c4 + 0] = v.x; Xs[r][c4 + 1] = v.y;
            Xs[r][c4 + 2] = v.z; Xs[r][c4 + 3] = v.w;
        }
    }
    __syncthreads();

    const int r = tid & 15;
    const int cg = tid >> 4;
    float4 acc = make_float4(0.f, 0.f, 0.f, 0.f);
    #pragma unroll 16
    for (int k = 0; k < FF; ++k) {
        const float xv = Xs[r][k];
        const float4 wv = *(const float4*)&Ws[k][cg * 4];
        acc.x += xv * wv.x; acc.y += xv * wv.y;
        acc.z += xv * wv.z; acc.w += xv * wv.w;
    }
    *(float4*)&g_feats[(rbase + r) * HD + cg * 4] = acc;

    __syncthreads();
    float* Fs = &Xs[0][0];
    Fs[r * 68 + cg * 4 + 0] = acc.x;
    Fs[r * 68 + cg * 4 + 1] = acc.y;
    Fs[r * 68 + cg * 4 + 2] = acc.z;
    Fs[r * 68 + cg * 4 + 3] = acc.w;
    __syncthreads();
    if (tid < 128) {
        const int rr = tid >> 3;
        const int h = tid & 7;
        float ds = 0.f, dn = 0.f;
        #pragma unroll
        for (int d = 0; d < DD; ++d) {
            const float f = Fs[rr * 68 + h * DD + d];
            ds += f * __ldg(&att_self[h * DD + d]);
            dn += f * __ldg(&att_neigh[h * DD + d]);
        }
        g_as[(rbase + rr) * HH + h] = ds;
        g_an[(rbase + rr) * HH + h] = dn;
    }
}

// ---------------- Kernel 2: per-row sparse softmax + aggregation ----------------
__global__ __launch_bounds__(256, 8) void gat_main_kernel(const float* __restrict__ A,
                                                          const float* __restrict__ bias,
                                                          float* __restrict__ out) {
    __shared__ int   s_idx[ECAP];            // 288 B
    __shared__ float s_an[HH][ECAP];         // 2.25 KB head-major (lane-partitioned 4B copies)
    __shared__ float s_w[HH][ECAP];          // 2.25 KB precomputed exp weights
    __shared__ float s_feats[ECAP][FPAD];    // 20.25 KB staged feats rows
    __shared__ int   s_wtot[8];
    __shared__ int   s_woff[8];
    __shared__ int   s_E;
    __shared__ float s_as[HH];

    const int i = blockIdx.x;
    const int tid = threadIdx.x;
    const int w = tid >> 5;
    const int lane = tid & 31;

    if (tid < HH) s_as[tid] = g_as[i * HH + tid];

    // --- coalesced A-row read: thread owns cols j = 1024*k + 4*tid + q ---
    const float4* Arow4 = (const float4*)(A + (size_t)i * NN);
    float4 v0 = Arow4[tid];
    float4 v1 = Arow4[256 + tid];
    float4 v2 = Arow4[512 + tid];
    float4 v3 = Arow4[768 + tid];

    // --- exact bitmask: 4 independent FFMA chains (A is exactly 0.0/1.0) ---
    float mf0 = fmaf(v0.y, 2.f, v0.x);
    mf0 = fmaf(v0.z, 4.f, mf0);  mf0 = fmaf(v0.w, 8.f, mf0);
    float mf1 = fmaf(v1.y, 2.f, v1.x);
    mf1 = fmaf(v1.z, 4.f, mf1);  mf1 = fmaf(v1.w, 8.f, mf1);
    float mf2 = fmaf(v2.y, 2.f, v2.x);
    mf2 = fmaf(v2.z, 4.f, mf2);  mf2 = fmaf(v2.w, 8.f, mf2);
    float mf3 = fmaf(v3.y, 2.f, v3.x);
    mf3 = fmaf(v3.z, 4.f, mf3);  mf3 = fmaf(v3.w, 8.f, mf3);
    unsigned mask = __float2uint_rn(mf0)
                  | (__float2uint_rn(mf1) << 4)
                  | (__float2uint_rn(mf2) << 8)
                  | (__float2uint_rn(mf3) << 12);
    const int c = __popc(mask);

    // --- warp scan + cross-warp scan ---
    int inc = c;
    #pragma unroll
    for (int off = 1; off < 32; off <<= 1) {
        int y = __shfl_up_sync(0xffffffffu, inc, off);
        if (lane >= off) inc += y;
    }
    if (lane == 31) s_wtot[w] = inc;
    __syncthreads();
    if (tid == 0) {
        int run = 0;
        #pragma unroll
        for (int q = 0; q < 8; ++q) { s_woff[q] = run; run += s_wtot[q]; }
        s_E = run;
    }
    __syncthreads();
    const int E = s_E;

    if (E <= ECAP) {
        // --- ffs-based compaction: work proportional to hits ---
        {
            int p = s_woff[w] + inc - c;
            unsigned m = mask;
            const int base = tid << 2;
            while (m) {
                const int b = __ffs(m) - 1;
                m &= m - 1;
                s_idx[p++] = ((b >> 2) << 10) | base | (b & 3);
            }
        }
        __syncthreads();

        // --- async staging, lane-partitioned: lanes 0-15 stage feats (16B each),
        //     lanes 16-23 stage a_n head-major (4B each) ---
        {
            const uint32_t sf_base = (uint32_t)__cvta_generic_to_shared(&s_feats[0][0]);
            const uint32_t sa_base = (uint32_t)__cvta_generic_to_shared(&s_an[0][0]);
            for (int e = w; e < E; e += 8) {
                const int j = s_idx[e];
                if (lane < 16)
                    cp_async16(sf_base + (e * FPAD + lane * 4) * 4, g_feats + j * HD + lane * 4);
                else if (lane < 16 + HH)
                    cp_async4(sa_base + ((lane - 16) * ECAP + e) * 4, g_an + j * HH + (lane - 16));
            }
            cp_async_commit();
        }
        cp_async_wait0();
        __syncthreads();

        // --- warp = head. Pre-pass: compute exp weights once (warp-private) ---
        const int h = w;
        const float as_i = s_as[h];
        float s = 0.f;
        for (int e = lane; e < E; e += 32) {
            float l = as_i + s_an[h][e];
            l = fmaxf(l, 0.2f * l);            // leaky_relu(0.2); logits O(0.1) -> no max-sub
            const float wt = __expf(l);
            s_w[h][e] = wt;
            s += wt;
        }
        #pragma unroll
        for (int o = 16; o; o >>= 1) s += __shfl_xor_sync(0xffffffffu, s, o);
        __syncwarp();                          // s_w visibility across lanes of this warp

        // --- aggregation: lane = stripe(0..3)*8 + dim(0..7); pure LDS+FFMA ---
        const int stripe = lane >> 3;
        const int d = lane & 7;
        const int hd = h * DD + d;
        float acc = 0.f;
        #pragma unroll 4
        for (int e = stripe; e < E; e += 4)
            acc = fmaf(s_w[h][e], s_feats[e][hd], acc);   // both conflict-free

        acc += __shfl_xor_sync(0xffffffffu, acc, 8);
        acc += __shfl_xor_sync(0xffffffffu, acc, 16);

        if (lane < HH) {
            const float inv = __fdividef(1.f, s);
            out[i * HD + h * DD + lane] =
                fmaxf(fmaf(acc, inv, __ldg(&bias[h * DD + lane])), 0.f);
        }
    } else {
        // --- slow fallback (statistically unreachable, correctness-preserving) ---
        __syncthreads();
        const int h = w;
        const float as_i = s_as[h];
        const float* Ar = A + (size_t)i * NN;

        float m = -3.0e38f;
        for (int j = lane; j < NN; j += 32) {
            if (Ar[j] > 0.5f) {
                float l = as_i + g_an[j * HH + h];
                l = fmaxf(l, 0.2f * l);
                m = fmaxf(m, l);
            }
        }
        #pragma unroll
        for (int o = 16; o; o >>= 1) m = fmaxf(m, __shfl_xor_sync(0xffffffffu, m, o));

        float s = 0.f;
        float acc[8] = {0.f, 0.f, 0.f, 0.f, 0.f, 0.f, 0.f, 0.f};
        for (int j = lane; j < NN; j += 32) {
            if (Ar[j] > 0.5f) {
                float l = as_i + g_an[j * HH + h];
                l = fmaxf(l, 0.2f * l);
                const float wt = __expf(l - m);
                s += wt;
                const float4* fp = (const float4*)(g_feats + j * HD + h * DD);
                const float4 f0 = fp[0], f1 = fp[1];
                acc[0] += wt * f0.x; acc[1] += wt * f0.y; acc[2] += wt * f0.z; acc[3] += wt * f0.w;
                acc[4] += wt * f1.x; acc[5] += wt * f1.y; acc[6] += wt * f1.z; acc[7] += wt * f1.w;
            }
        }
        #pragma unroll
        for (int o = 16; o; o >>= 1) {
            s += __shfl_xor_sync(0xffffffffu, s, o);
            #pragma unroll
            for (int dd = 0; dd < 8; ++dd) acc[dd] += __shfl_xor_sync(0xffffffffu, acc[dd], o);
        }
        if (lane == 0) {
            const float inv = 1.0f / s;
            #pragma unroll
            for (int dd = 0; dd < 8; ++dd)
                out[i * HD + h * DD + dd] = fmaxf(acc[dd] * inv + bias[h * DD + dd], 0.f);
        }
    }
}

extern "C" void kernel_launch(void* const* d_in, const int* in_sizes, int n_in,
                              void* d_out, int out_size) {
    const float* X         = (const float*)d_in[0];  // [4096,128]
    const float* A         = (const float*)d_in[1];  // [4096,4096]
    const float* W         = (const float*)d_in[2];  // [128,64]
    const float* att_self  = (const float*)d_in[3];  // [1,8,8]
    const float* att_neigh = (const float*)d_in[4];  // [1,8,8]
    const float* bias      = (const float*)d_in[5];  // [1,8,8]
    float* out             = (float*)d_out;          // [4096,64]

    feats_att_kernel<<<NN / 16, 256>>>(X, W, att_self, att_neigh);
    gat_main_kernel<<<NN, 256>>>(A, bias, out);
}

// round 11
// speedup vs baseline: 1.0696x; 1.0696x over previous
#include <cuda_runtime.h>
#include <cstdint>

#define NN 4096
#define FF 128
#define HH 8
#define DD 8
#define HD 64
#define ECAP 72     // fast-path edge cap (mean E~41, sigma~6.4; slow fallback keeps correctness for outliers)
#define FPAD 68     // s_feats row stride: 68 mod 32 == 4 -> 8 stripes x 4 dims span 32 distinct banks
#define APAD 9      // s_an row stride: 9 mod 32 -> 8 stripes on distinct banks

__device__ float g_feats[NN * HD];
__device__ float g_as[NN * HH];
__device__ float g_an[NN * HH];

__device__ __forceinline__ void cp_async4(uint32_t dst, const void* src) {
    asm volatile("cp.async.ca.shared.global [%0], [%1], 4;" :: "r"(dst), "l"(src));
}
__device__ __forceinline__ void cp_async16(uint32_t dst, const void* src) {
    asm volatile("cp.async.ca.shared.global [%0], [%1], 16;" :: "r"(dst), "l"(src));
}
__device__ __forceinline__ void cp_async_commit() {
    asm volatile("cp.async.commit_group;");
}
__device__ __forceinline__ void cp_async_wait0() {
    asm volatile("cp.async.wait_group 0;");
}

// ---------------- Kernel 1: feats = X @ W  fused with a_s / a_n epilogue ----------------
__global__ __launch_bounds__(256) void feats_att_kernel(const float* __restrict__ X,
                                                        const float* __restrict__ W,
                                                        const float* __restrict__ att_self,
                                                        const float* __restrict__ att_neigh) {
    __shared__ float Ws[FF][HD];      // 32 KB
    __shared__ float Xs[16][133];     // stride 133; reused as Fs[16][68] in epilogue
    const int tid = threadIdx.x;
    const int rbase = blockIdx.x * 16;

    {
        const float4* Wv = (const float4*)W;
        float4* Wsv = (float4*)&Ws[0][0];
        #pragma unroll
        for (int k = 0; k < 8; ++k) Wsv[tid + k * 256] = Wv[tid + k * 256];
    }
    {
        #pragma unroll
        for (int k = 0; k < 2; ++k) {
            const int li = tid + k * 256;
            const int r = li >> 5;
            const int c4 = (li & 31) << 2;
            float4 v = *(const float4*)&X[(rbase + r) * FF + c4];
            Xs[r][c4 + 0] = v.x; Xs[r][c4 + 1] = v.y;
            Xs[r][c4 + 2] = v.z; Xs[r][c4 + 3] = v.w;
        }
    }
    __syncthreads();

    const int r = tid & 15;
    const int cg = tid >> 4;
    float4 acc = make_float4(0.f, 0.f, 0.f, 0.f);
    #pragma unroll 16
    for (int k = 0; k < FF; ++k) {
        const float xv = Xs[r][k];
        const float4 wv = *(const float4*)&Ws[k][cg * 4];
        acc.x += xv * wv.x; acc.y += xv * wv.y;
        acc.z += xv * wv.z; acc.w += xv * wv.w;
    }
    *(float4*)&g_feats[(rbase + r) * HD + cg * 4] = acc;

    __syncthreads();
    float* Fs = &Xs[0][0];
    Fs[r * 68 + cg * 4 + 0] = acc.x;
    Fs[r * 68 + cg * 4 + 1] = acc.y;
    Fs[r * 68 + cg * 4 + 2] = acc.z;
    Fs[r * 68 + cg * 4 + 3] = acc.w;
    __syncthreads();
    if (tid < 128) {
        const int rr = tid >> 3;
        const int h = tid & 7;
        float ds = 0.f, dn = 0.f;
        #pragma unroll
        for (int d = 0; d < DD; ++d) {
            const float f = Fs[rr * 68 + h * DD + d];
            ds += f * __ldg(&att_self[h * DD + d]);
            dn += f * __ldg(&att_neigh[h * DD + d]);
        }
        g_as[(rbase + rr) * HH + h] = ds;
        g_an[(rbase + rr) * HH + h] = dn;
    }
}

// ---------------- Kernel 2: per-row sparse softmax + aggregation ----------------
__global__ __launch_bounds__(256, 8) void gat_main_kernel(const float* __restrict__ A,
                                                          const float* __restrict__ bias,
                                                          float* __restrict__ out) {
    __shared__ int   s_idx[ECAP];            // 288 B
    __shared__ float s_an[ECAP][APAD];       // 2.6 KB edge-major, stride 9 (stripe-conflict-free)
    __shared__ float s_feats[ECAP][FPAD];    // 19.1 KB staged feats rows
    __shared__ int   s_wtot[8];
    __shared__ float s_as[HH];

    const int i = blockIdx.x;
    const int tid = threadIdx.x;
    const int w = tid >> 5;
    const int lane = tid & 31;

    if (tid < HH) s_as[tid] = g_as[i * HH + tid];

    // --- coalesced A-row read: thread owns cols j = 1024*k + 4*tid + q ---
    const float4* Arow4 = (const float4*)(A + (size_t)i * NN);
    float4 v0 = Arow4[tid];
    float4 v1 = Arow4[256 + tid];
    float4 v2 = Arow4[512 + tid];
    float4 v3 = Arow4[768 + tid];

    // --- exact bitmask: 4 independent FFMA chains (A is exactly 0.0/1.0) ---
    float mf0 = fmaf(v0.y, 2.f, v0.x);
    mf0 = fmaf(v0.z, 4.f, mf0);  mf0 = fmaf(v0.w, 8.f, mf0);
    float mf1 = fmaf(v1.y, 2.f, v1.x);
    mf1 = fmaf(v1.z, 4.f, mf1);  mf1 = fmaf(v1.w, 8.f, mf1);
    float mf2 = fmaf(v2.y, 2.f, v2.x);
    mf2 = fmaf(v2.z, 4.f, mf2);  mf2 = fmaf(v2.w, 8.f, mf2);
    float mf3 = fmaf(v3.y, 2.f, v3.x);
    mf3 = fmaf(v3.z, 4.f, mf3);  mf3 = fmaf(v3.w, 8.f, mf3);
    unsigned mask = __float2uint_rn(mf0)
                  | (__float2uint_rn(mf1) << 4)
                  | (__float2uint_rn(mf2) << 8)
                  | (__float2uint_rn(mf3) << 12);
    const int c = __popc(mask);

    // --- warp-level inclusive scan of per-thread counts ---
    int inc = c;
    #pragma unroll
    for (int off = 1; off < 32; off <<= 1) {
        int y = __shfl_up_sync(0xffffffffu, inc, off);
        if (lane >= off) inc += y;
    }
    if (lane == 31) s_wtot[w] = inc;
    __syncthreads();

    // --- every warp reconstructs all 8 warp totals (no 2nd barrier, no serial thread) ---
    int raw = (lane < 8) ? s_wtot[lane] : 0;
    int sc = raw;
    #pragma unroll
    for (int o = 1; o < 8; o <<= 1) {
        int y = __shfl_up_sync(0xffffffffu, sc, o);
        if (lane >= o) sc += y;
    }
    const int E = __shfl_sync(0xffffffffu, sc, 7);
    const int woff = __shfl_sync(0xffffffffu, sc, w) - __shfl_sync(0xffffffffu, raw, w);

    if (E <= ECAP) {
        // --- ffs-based compaction: work proportional to hits ---
        {
            int p = woff + inc - c;
            unsigned m = mask;
            const int base = tid << 2;
            while (m) {
                const int b = __ffs(m) - 1;
                m &= m - 1;
                s_idx[p++] = ((b >> 2) << 10) | base | (b & 3);
            }
        }
        __syncthreads();

        // --- async staging: warp per edge; lanes 0-15 stage feats (16B), lanes 16-23 stage a_n (4B) ---
        {
            const uint32_t sf_base = (uint32_t)__cvta_generic_to_shared(&s_feats[0][0]);
            const uint32_t sa_base = (uint32_t)__cvta_generic_to_shared(&s_an[0][0]);
            for (int e = w; e < E; e += 8) {
                const int j = s_idx[e];
                if (lane < 16)
                    cp_async16(sf_base + (e * FPAD + lane * 4) * 4, g_feats + j * HD + lane * 4);
                else if (lane < 16 + HH)
                    cp_async4(sa_base + (e * APAD + (lane - 16)) * 4, g_an + j * HH + (lane - 16));
            }
            cp_async_commit();
        }
        cp_async_wait0();
        __syncthreads();

        // --- warp = head; lane = stripe(0..7)*4 + dim(0..3); each lane covers dims d and d+4 ---
        const int h = w;
        const int stripe = lane >> 2;
        const int d = lane & 3;
        const float as_i = s_as[h];
        const int hd = h * DD + d;
        float acc0 = 0.f, acc1 = 0.f, s = 0.f;
        #pragma unroll 2
        for (int e = stripe; e < E; e += 8) {
            float l = as_i + s_an[e][h];           // 8 distinct banks (APAD=9), 4-lane bcast: 1 wf
            l = fmaxf(l, 0.2f * l);                // leaky_relu(0.2); logits O(0.1) -> no max-sub
            const float wt = __expf(l);            // same-exp lanes share the warp instruction
            s += wt;
            acc0 = fmaf(wt, s_feats[e][hd],     acc0);   // conflict-free (FPAD=68)
            acc1 = fmaf(wt, s_feats[e][hd + 4], acc1);
        }
        // reduce across the 8 stripes
        #pragma unroll
        for (int o = 4; o <= 16; o <<= 1) {
            acc0 += __shfl_xor_sync(0xffffffffu, acc0, o);
            acc1 += __shfl_xor_sync(0xffffffffu, acc1, o);
            s    += __shfl_xor_sync(0xffffffffu, s, o);
        }

        if (lane < 4) {
            const float inv = __fdividef(1.f, s);
            out[i * HD + h * DD + lane] =
                fmaxf(fmaf(acc0, inv, __ldg(&bias[h * DD + lane])), 0.f);
            out[i * HD + h * DD + lane + 4] =
                fmaxf(fmaf(acc1, inv, __ldg(&bias[h * DD + lane + 4])), 0.f);
        }
    } else {
        // --- slow fallback (statistically unreachable, correctness-preserving) ---
        __syncthreads();
        const int h = w;
        const float as_i = s_as[h];
        const float* Ar = A + (size_t)i * NN;

        float m = -3.0e38f;
        for (int j = lane; j < NN; j += 32) {
            if (Ar[j] > 0.5f) {
                float l = as_i + g_an[j * HH + h];
                l = fmaxf(l, 0.2f * l);
                m = fmaxf(m, l);
            }
        }
        #pragma unroll
        for (int o = 16; o; o >>= 1) m = fmaxf(m, __shfl_xor_sync(0xffffffffu, m, o));

        float s = 0.f;
        float acc[8] = {0.f, 0.f, 0.f, 0.f, 0.f, 0.f, 0.f, 0.f};
        for (int j = lane; j < NN; j += 32) {
            if (Ar[j] > 0.5f) {
                float l = as_i + g_an[j * HH + h];
                l = fmaxf(l, 0.2f * l);
                const float wt = __expf(l - m);
                s += wt;
                const float4* fp = (const float4*)(g_feats + j * HD + h * DD);
                const float4 f0 = fp[0], f1 = fp[1];
                acc[0] += wt * f0.x; acc[1] += wt * f0.y; acc[2] += wt * f0.z; acc[3] += wt * f0.w;
                acc[4] += wt * f1.x; acc[5] += wt * f1.y; acc[6] += wt * f1.z; acc[7] += wt * f1.w;
            }
        }
        #pragma unroll
        for (int o = 16; o; o >>= 1) {
            s += __shfl_xor_sync(0xffffffffu, s, o);
            #pragma unroll
            for (int dd = 0; dd < 8; ++dd) acc[dd] += __shfl_xor_sync(0xffffffffu, acc[dd], o);
        }
        if (lane == 0) {
            const float inv = 1.0f / s;
            #pragma unroll
            for (int dd = 0; dd < 8; ++dd)
                out[i * HD + h * DD + dd] = fmaxf(acc[dd] * inv + bias[h * DD + dd], 0.f);
        }
    }
}

extern "C" void kernel_launch(void* const* d_in, const int* in_sizes, int n_in,
                              void* d_out, int out_size) {
    const float* X         = (const float*)d_in[0];  // [4096,128]
    const float* A         = (const float*)d_in[1];  // [4096,4096]
    const float* W         = (const float*)d_in[2];  // [128,64]
    const float* att_self  = (const float*)d_in[3];  // [1,8,8]
    const float* att_neigh = (const float*)d_in[4];  // [1,8,8]
    const float* bias      = (const float*)d_in[5];  // [1,8,8]
    float* out             = (float*)d_out;          // [4096,64]

    feats_att_kernel<<<NN / 16, 256>>>(X, W, att_self, att_neigh);
    gat_main_kernel<<<NN, 256>>>(A, bias, out);
}